// round 14
// baseline (speedup 1.0000x reference)
#include <cuda_runtime.h>
#include <cuda_fp16.h>
#include <math.h>
#include <stdint.h>

#define TLEN 32768
#define NB 2
#define RC 64
#define GC 128
#define SC 64
#define AC 80
#define NLAYERS 30
#define SQRT_HALF 0.70710678118654752440f
#define SQRT_INV_L 0.18257418583505537115f

// ======================= scratch (device globals) ============================
__device__ float g_h32a[NB * TLEN * RC];                    // fp32 residual carry
__device__ float g_h32b[NB * TLEN * RC];
__device__ __align__(16) __half g_h16a[NB * TLEN * RC];     // fp16 MMA snapshot
__device__ __align__(16) __half g_h16b[NB * TLEN * RC];
__device__ float g_skip[NB * TLEN * SC];
__device__ __align__(16) __half g_c16[NB * 2 * TLEN * 64];
__device__ __align__(16) __half g_Wg16[NLAYERS * 5 * 128 * 64];
__device__ __align__(16) __half g_W216[NLAYERS * 128 * 64];

// ======================= helpers =============================================
__device__ __forceinline__ uint32_t smem_u32(const void* p) {
    uint32_t a;
    asm("{ .reg .u64 t; cvta.to.shared.u64 t, %1; cvt.u32.u64 %0, t; }" : "=r"(a) : "l"(p));
    return a;
}
__device__ __forceinline__ void ldm4(uint32_t* r, uint32_t addr) {
    asm volatile("ldmatrix.sync.aligned.m8n8.x4.shared.b16 {%0,%1,%2,%3}, [%4];"
        : "=r"(r[0]), "=r"(r[1]), "=r"(r[2]), "=r"(r[3]) : "r"(addr));
}
__device__ __forceinline__ void mma16816(float* d, const uint32_t* a, uint32_t b0, uint32_t b1) {
    asm volatile("mma.sync.aligned.m16n8k16.row.col.f32.f16.f16.f32 "
        "{%0,%1,%2,%3}, {%4,%5,%6,%7}, {%8,%9}, {%0,%1,%2,%3};"
        : "+f"(d[0]), "+f"(d[1]), "+f"(d[2]), "+f"(d[3])
        : "r"(a[0]), "r"(a[1]), "r"(a[2]), "r"(a[3]), "r"(b0), "r"(b1));
}
__device__ __forceinline__ void cpa16(uint32_t dst, const void* src, int srcsz) {
    asm volatile("cp.async.ca.shared.global [%0], [%1], 16, %2;"
        :: "r"(dst), "l"(src), "r"(srcsz) : "memory");
}
#define CP_COMMIT() asm volatile("cp.async.commit_group;" ::: "memory")
#define CP_WAIT0()  asm volatile("cp.async.wait_group 0;" ::: "memory")
#define CP_WAIT1()  asm volatile("cp.async.wait_group 1;" ::: "memory")

__device__ __forceinline__ uint32_t packh2(float lo, float hi) {
    __half2 t = __floats2half2_rn(lo, hi);
    return *(uint32_t*)&t;
}

// ======================= fused conditioning ==================================
__global__ void cond_fused(const float* __restrict__ c, const float* __restrict__ Wc,
                           const float* __restrict__ Wup,
                           __half* __restrict__ P16) {
    extern __shared__ float us[];
    const int b  = blockIdx.y;
    const int t0 = blockIdx.x * 128;
    const int tid = threadIdx.x;   // 256

    const int u0 = (t0 - 4) >> 2;
    const int un = ((t0 + 131) >> 2) - u0 + 1;
    const int v0 = (u0 - 4) >> 2;
    const int vn = ((u0 + un - 1 + 4) >> 2) - v0 + 1;
    const int w0 = (v0 - 4) >> 2;
    const int wn = ((v0 + vn - 1 + 4) >> 2) - w0 + 1;
    const int f0 = (w0 - 4) >> 2;
    const int fn = ((w0 + wn - 1 + 4) >> 2) - f0 + 1;

    float* y0 = us;
    float* y1 = y0 + 80 * 6;
    float* s1 = y1 + 80 * 8;
    float* s2 = s1 + 80 * 8;
    float* s3 = s2 + 80 * 14;
    float* s4 = s3 + 80 * 36;

    for (int i = tid; i < 80 * fn; i += 256) {
        int ch = i / fn, ff = i - ch * fn;
        int f = f0 + ff;
        y0[ch * 6 + ff] = (f >= 0 && f < 128) ? c[((size_t)b * 80 + ch) * 128 + f] : 0.f;
    }
    __syncthreads();
    for (int i = tid; i < 80 * fn; i += 256) {
        int o = i / fn, ff = i - o * fn;
        float acc = 0.f;
        #pragma unroll 4
        for (int k = 0; k < 80; ++k) acc += Wc[o * 80 + k] * y0[k * 6 + ff];
        y1[o * 8 + ff] = acc;
    }
    __syncthreads();
    for (int i = tid; i < 80 * wn; i += 256) {
        int o = i / wn, wi = i - o * wn;
        int w = w0 + wi;
        float acc = 0.f;
        #pragma unroll
        for (int k = 0; k < 9; ++k) {
            int rr = w - 4 + k;
            if (rr >= 0 && rr < 512) acc += Wup[k] * y1[o * 8 + ((rr >> 2) - f0)];
        }
        s1[o * 8 + wi] = acc;
    }
    __syncthreads();
    for (int i = tid; i < 80 * vn; i += 256) {
        int o = i / vn, vi = i - o * vn;
        int v = v0 + vi;
        float acc = 0.f;
        #pragma unroll
        for (int k = 0; k < 9; ++k) {
            int rr = v - 4 + k;
            if (rr >= 0 && rr < 2048) acc += Wup[9 + k] * s1[o * 8 + ((rr >> 2) - w0)];
        }
        s2[o * 14 + vi] = acc;
    }
    __syncthreads();
    for (int i = tid; i < 80 * un; i += 256) {
        int o = i / un, ui = i - o * un;
        int u = u0 + ui;
        float acc = 0.f;
        #pragma unroll
        for (int k = 0; k < 9; ++k) {
            int rr = u - 4 + k;
            if (rr >= 0 && rr < 8192) acc += Wup[18 + k] * s2[o * 14 + ((rr >> 2) - v0)];
        }
        s3[o * 36 + ui] = acc;
    }
    __syncthreads();
    for (int i = tid; i < 80 * 128; i += 256) {
        int o = i >> 7, tl = i & 127;
        int t = t0 + tl;
        float acc = 0.f;
        #pragma unroll
        for (int k = 0; k < 9; ++k) {
            int rr = t - 4 + k;
            if (rr >= 0 && rr < TLEN) acc += Wup[27 + k] * s3[o * 36 + ((rr >> 2) - u0)];
        }
        s4[o * 128 + tl] = acc;
    }
    __syncthreads();
    for (int i = tid; i < 128 * 64; i += 256) {
        int tl = i >> 6, j = i & 63;
        size_t o0 = (((size_t)b * 2 + 0) * TLEN + (t0 + tl)) * 64 + j;
        size_t o1 = (((size_t)b * 2 + 1) * TLEN + (t0 + tl)) * 64 + j;
        float v0f = s4[j * 128 + tl];
        float v1f = (j < 16) ? s4[(64 + j) * 128 + tl] : 0.f;
        P16[o0] = __float2half(v0f);
        P16[o1] = __float2half(v1f);
    }
}

// ======================= weight prepack ======================================
__global__ void prepack_w(const float* __restrict__ Wd, const float* __restrict__ Wa,
                          const float* __restrict__ Ws, const float* __restrict__ Wr,
                          __half* __restrict__ Wg16, __half* __restrict__ W216) {
    const int N1 = NLAYERS * 5 * 128 * 64;
    const int N2 = NLAYERS * 128 * 64;
    int i = blockIdx.x * blockDim.x + threadIdx.x;
    if (i < N1) {
        int kl = i & 63;
        int r  = (i >> 6) & 127;
        int lc = i >> 13;
        int cc = lc % 5;
        int l  = lc / 5;
        int j  = ((r >> 4) << 3) + (((r & 7) >> 1) << 1) + ((r >> 3) & 1);
        int ch = (r & 1) ? (64 + j) : j;
        float w;
        if (cc < 3)       w = Wd[(((size_t)l * GC + ch) * RC + kl) * 3 + cc];
        else if (cc == 3) w = Wa[((size_t)l * GC + ch) * AC + kl];
        else              w = (kl < AC - 64) ? Wa[((size_t)l * GC + ch) * AC + 64 + kl] : 0.f;
        Wg16[i] = __float2half(w);
    } else if (i - N1 < N2) {
        int i2 = i - N1;
        int k  = i2 & 63;
        int r2 = (i2 >> 6) & 127;
        int l  = i2 >> 13;
        float w = (r2 < 64) ? Ws[((size_t)l * SC + r2) * 64 + k]
                            : Wr[((size_t)l * RC + (r2 - 64)) * 64 + k];
        W216[i2] = __float2half(w);
    }
}

__global__ void first_pack(const float* __restrict__ x,
                           const float* __restrict__ Wf, const float* __restrict__ bf,
                           float* __restrict__ h32, __half* __restrict__ h16,
                           float* __restrict__ skip) {
    int idx = blockIdx.x * blockDim.x + threadIdx.x;
    if (idx >= NB * TLEN * RC) return;
    int j = idx & 63;
    int t = (idx >> 6) & (TLEN - 1);
    int b = idx >> 21;
    float v = Wf[j] * x[(size_t)b * TLEN + t] + bf[j];
    h32[idx] = v;
    h16[idx] = __float2half(v);
    skip[idx] = 0.f;
}

// ======================= fused residual layer ================================
// 128-t tile, 8 warps m32n64; W double buffer + contiguous 256-row D region.
#define STRIDE 144
#define RSZ (128 * STRIDE)
#define OFF_W0  0
#define OFF_D0  (2 * RSZ)
#define OFF_BD  (4 * RSZ)
#define SMEM_NEED (OFF_BD + 1024)

__global__ __launch_bounds__(256, 2)
void layer_mma(int l, int dil,
               const float* __restrict__ hin32, float* __restrict__ hout32,
               const __half* __restrict__ hin16, __half* __restrict__ hout16,
               const __half* __restrict__ c16,
               float* __restrict__ skip,
               const __half* __restrict__ Wg16, const __half* __restrict__ W216,
               const float* __restrict__ bd, const float* __restrict__ bs,
               const float* __restrict__ br) {
    extern __shared__ char smem_c[];
    const uint32_t sb = smem_u32(smem_c);
    float* sbd = (float*)(smem_c + OFF_BD);

    const int tid  = threadIdx.x;
    const int warp = tid >> 5;
    const int lane = tid & 31;
    const int b    = blockIdx.y;
    const int t0   = blockIdx.x * 128;

    const int wm    = warp & 3;       // t-tile (32 rows)
    const int wn    = warp >> 2;      // n-tile (64 cols)
    const int mbase = wm * 32;
    const int nbase = wn * 64;

    const int lrow  = lane & 15;
    const int lkoff = (lane >> 4) * 16;
    const int q     = lane & 3;
    const int r     = lane >> 2;

    // biases: bd[0..127], bs[128..191], br[192..255]
    if (tid < 128)      sbd[tid] = bd[l * GC + tid];
    else if (tid < 192) sbd[tid] = bs[l * SC + tid - 128];
    else                sbd[tid] = br[l * RC + tid - 192];

    // ---- staging helpers ----
    auto stage_W = [&](int chunk, int buf) {          // GEMM1 weight chunk
        const char* wb = (const char*)(Wg16 + (((size_t)l * 5 + chunk) * 128) * 64);
        #pragma unroll
        for (int it = 0; it < 4; ++it) {
            const int p = it * 256 + tid;
            const int row = p >> 3, j = p & 7;
            if (chunk == 4 && j >= 2) continue;
            cpa16(sb + OFF_W0 + buf * RSZ + (uint32_t)row * STRIDE + j * 16, wb + p * 16, 16);
        }
    };
    auto stage_condD = [&](int cc, int dreg) {        // cond data chunk cc into D region dreg
        #pragma unroll
        for (int it = 0; it < 4; ++it) {
            const int p = it * 256 + tid;
            const int row = p >> 3, j = p & 7;
            if (cc == 1 && j >= 2) continue;
            const char* src = (const char*)c16
                + (((size_t)b * 2 + cc) * TLEN + (t0 + row)) * 128 + j * 16;
            cpa16(sb + OFF_D0 + dreg * RSZ + (uint32_t)row * STRIDE + j * 16, src, 16);
        }
    };
    auto stage_DU = [&](int g0, int nrows) {          // h union rows g0..g0+nrows-1, t = t0-dil+g
        for (int p = tid; p < nrows * 8; p += 256) {
            const int g = g0 + (p >> 3), j = p & 7;
            const int t = t0 - dil + g;
            const char* src; int sz = 16;
            if (t >= 0 && t < TLEN)
                src = (const char*)hin16 + ((size_t)b * TLEN + t) * 128 + j * 16;
            else { src = (const char*)hin16; sz = 0; }
            cpa16(sb + OFF_D0 + (uint32_t)g * STRIDE + j * 16, src, sz);
        }
    };
    auto stage_tapD = [&](int c, int buf) {           // path-B per-tap data
        #pragma unroll
        for (int it = 0; it < 4; ++it) {
            const int p = it * 256 + tid;
            const int row = p >> 3, j = p & 7;
            const char* src; int sz = 16;
            int tg = t0 + row + (c - 1) * dil;
            if (tg >= 0 && tg < TLEN)
                src = (const char*)hin16 + ((size_t)b * TLEN + tg) * 128 + j * 16;
            else { src = (const char*)hin16; sz = 0; }
            cpa16(sb + OFF_D0 + buf * RSZ + (uint32_t)row * STRIDE + j * 16, src, sz);
        }
    };
    auto stage_w2 = [&](int buf) {
        const char* wb = (const char*)(W216 + (size_t)l * 128 * 64);
        #pragma unroll
        for (int it = 0; it < 4; ++it) {
            const int p = it * 256 + tid;
            const int row = p >> 3, j = p & 7;
            cpa16(sb + OFF_W0 + buf * RSZ + (uint32_t)row * STRIDE + j * 16, wb + p * 16, 16);
        }
    };

    float acc[16][4];
    #pragma unroll
    for (int i = 0; i < 16; ++i)
        #pragma unroll
        for (int j2 = 0; j2 < 4; ++j2) acc[i][j2] = 0.f;

    auto do_mma = [&](uint32_t abase, uint32_t wbase, int nks) {
        for (int ks = 0; ks < nks; ++ks) {
            uint32_t a0f[4], a1f[4];
            ldm4(a0f, abase + ks * 32);
            ldm4(a1f, abase + 16 * STRIDE + ks * 32);
            uint32_t bf4[4][4];
            #pragma unroll
            for (int i = 0; i < 4; ++i)
                ldm4(bf4[i], wbase + (uint32_t)(nbase + i * 16 + lrow) * STRIDE + lkoff + ks * 32);
            #pragma unroll
            for (int i = 0; i < 4; ++i) {
                mma16816(acc[i * 2],         a0f, bf4[i][0], bf4[i][2]);
                mma16816(acc[i * 2 + 1],     a0f, bf4[i][1], bf4[i][3]);
            }
            #pragma unroll
            for (int i = 0; i < 4; ++i) {
                mma16816(acc[8 + i * 2],     a1f, bf4[i][0], bf4[i][2]);
                mma16816(acc[8 + i * 2 + 1], a1f, bf4[i][1], bf4[i][3]);
            }
        }
    };

    const uint32_t arow = (uint32_t)(mbase + lrow);
    uint32_t zoff;

    if (dil <= 64) {
        // ======== path A: merged cond phase, then union taps ========
        stage_W(3, 0); stage_condD(0, 0); CP_COMMIT();   // G1: cond-lo
        stage_W(4, 1); stage_condD(1, 1); CP_COMMIT();   // G2: cond-hi
        CP_WAIT0(); __syncthreads();
        // all 5 cond k-steps in one phase (same accumulation order as before)
        do_mma(sb + OFF_D0 + arow * STRIDE + lkoff, sb + OFF_W0, 4);
        do_mma(sb + OFF_D0 + RSZ + arow * STRIDE + lkoff, sb + OFF_W0 + RSZ, 1);
        __syncthreads();
        // full union + tap0 weights in one group
        stage_W(0, 0); stage_DU(0, 128 + 2 * dil); CP_COMMIT();   // G3
        CP_WAIT0(); __syncthreads();
        do_mma(sb + OFF_D0 + arow * STRIDE + lkoff, sb + OFF_W0, 4);           // tap0
        __syncthreads();
        stage_W(1, 1); CP_COMMIT();                      // G4
        CP_WAIT0(); __syncthreads();
        do_mma(sb + OFF_D0 + (arow + dil) * STRIDE + lkoff, sb + OFF_W0 + RSZ, 4); // tap1
        __syncthreads();
        stage_W(2, 0); CP_COMMIT();                      // G5
        CP_WAIT0(); __syncthreads();
        do_mma(sb + OFF_D0 + (arow + 2 * dil) * STRIDE + lkoff, sb + OFF_W0, 4);   // tap2
        __syncthreads();
        stage_w2(1); CP_COMMIT();                        // G6 (overlaps gate)
        zoff = OFF_D0;
    } else {
        // ======== path B: per-tap pipeline (unchanged) ========
        stage_W(0, 0); stage_tapD(0, 0); CP_COMMIT();
        stage_W(1, 1); stage_tapD(1, 1); CP_COMMIT();
        for (int c = 0; c < 5; ++c) {
            CP_WAIT1(); __syncthreads();
            const int buf = c & 1;
            do_mma(sb + OFF_D0 + buf * RSZ + arow * STRIDE + lkoff,
                   sb + OFF_W0 + buf * RSZ, (c == 4) ? 1 : 4);
            __syncthreads();
            if (c < 3) {
                const int nc = c + 2, nbuf = nc & 1;
                stage_W(nc, nbuf);
                if (nc < 3) stage_tapD(nc, nbuf);
                else        stage_condD(nc - 3, nbuf);
                CP_COMMIT();
            } else if (c == 3) { stage_w2(1); CP_COMMIT(); }
        }
        zoff = OFF_D0 + RSZ;
    }

    // ---------------- gate -> z (fp16) ----------------
    #pragma unroll
    for (int mf = 0; mf < 2; ++mf) {
        const int tr0 = mbase + mf * 16 + r;
        #pragma unroll
        for (int i = 0; i < 4; ++i) {
            #pragma unroll
            for (int p = 0; p < 2; ++p) {
                const int j = (wn * 4 + i) * 8 + 2 * q + p;
                const float ba = sbd[j], bb = sbd[64 + j];
                const float* a = acc[(mf * 4 + i) * 2 + p];
                #pragma unroll
                for (int h = 0; h < 2; ++h) {
                    float xa = a[h * 2 + 0] + ba;
                    float xb = a[h * 2 + 1] + bb;
                    float e2 = __expf(-2.f * fabsf(xa));
                    float th = copysignf(__fdividef(1.f - e2, 1.f + e2), xa);
                    float sg = __fdividef(1.f, 1.f + __expf(-xb));
                    float z  = th * sg;
                    const int tr = tr0 + h * 8;
                    *(__half*)(smem_c + zoff + (uint32_t)tr * STRIDE + j * 2) = __float2half(z);
                }
            }
        }
    }

    CP_WAIT0();
    __syncthreads();

    // ---------------- GEMM2: z * W2^T (W buf1) ----------------
    float acc2[16][4];
    #pragma unroll
    for (int i = 0; i < 16; ++i)
        #pragma unroll
        for (int j2 = 0; j2 < 4; ++j2) acc2[i][j2] = 0.f;

    #pragma unroll
    for (int ks = 0; ks < 4; ++ks) {
        uint32_t a0f[4], a1f[4];
        const uint32_t a0 = sb + zoff + arow * STRIDE + lkoff + ks * 32;
        ldm4(a0f, a0);
        ldm4(a1f, a0 + 16 * STRIDE);
        uint32_t wf4[4][4];
        #pragma unroll
        for (int i = 0; i < 4; ++i)
            ldm4(wf4[i], sb + OFF_W0 + RSZ + (uint32_t)(nbase + i * 16 + lrow) * STRIDE + lkoff + ks * 32);
        #pragma unroll
        for (int i = 0; i < 4; ++i) {
            mma16816(acc2[i * 2],         a0f, wf4[i][0], wf4[i][2]);
            mma16816(acc2[i * 2 + 1],     a0f, wf4[i][1], wf4[i][3]);
        }
        #pragma unroll
        for (int i = 0; i < 4; ++i) {
            mma16816(acc2[8 + i * 2],     a1f, wf4[i][0], wf4[i][2]);
            mma16816(acc2[8 + i * 2 + 1], a1f, wf4[i][1], wf4[i][3]);
        }
    }

    // ---------------- epilogue (warp-uniform, coalesced [t][ch]) -------------
    if (wn == 0) {                         // out-ch 0..63 -> skip
        #pragma unroll
        for (int mf = 0; mf < 2; ++mf) {
            const int trowA = t0 + mbase + mf * 16 + r;
            const int trowB = trowA + 8;
            #pragma unroll
            for (int i = 0; i < 4; ++i) {
                #pragma unroll
                for (int p = 0; p < 2; ++p) {
                    const int ch = i * 16 + p * 8 + 2 * q;
                    const float* d = acc2[(mf * 4 + i) * 2 + p];
                    float bs0 = sbd[128 + ch], bs1 = sbd[128 + ch + 1];
                    float2* p1 = (float2*)&skip[((size_t)b * TLEN + trowA) * 64 + ch];
                    float2* p2 = (float2*)&skip[((size_t)b * TLEN + trowB) * 64 + ch];
                    float2 v1 = *p1, v2 = *p2;
                    v1.x += d[0] + bs0; v1.y += d[1] + bs1;
                    v2.x += d[2] + bs0; v2.y += d[3] + bs1;
                    *p1 = v1; *p2 = v2;
                }
            }
        }
    } else {                               // out-ch 64..127 -> residual
        #pragma unroll
        for (int mf = 0; mf < 2; ++mf) {
            const int trowA = t0 + mbase + mf * 16 + r;
            const int trowB = trowA + 8;
            #pragma unroll
            for (int i = 0; i < 4; ++i) {
                #pragma unroll
                for (int p = 0; p < 2; ++p) {
                    const int ch = i * 16 + p * 8 + 2 * q;
                    const float* d = acc2[(mf * 4 + i) * 2 + p];
                    float br0 = sbd[192 + ch], br1 = sbd[192 + ch + 1];
                    size_t e1 = ((size_t)b * TLEN + trowA) * 64 + ch;
                    size_t e2 = ((size_t)b * TLEN + trowB) * 64 + ch;
                    float2 i1 = *(const float2*)&hin32[e1];
                    float2 i2 = *(const float2*)&hin32[e2];
                    float h10 = (d[0] + br0 + i1.x) * SQRT_HALF;
                    float h11 = (d[1] + br1 + i1.y) * SQRT_HALF;
                    float h20 = (d[2] + br0 + i2.x) * SQRT_HALF;
                    float h21 = (d[3] + br1 + i2.y) * SQRT_HALF;
                    *(float2*)&hout32[e1] = make_float2(h10, h11);
                    *(float2*)&hout32[e2] = make_float2(h20, h21);
                    *(uint32_t*)&hout16[e1] = packh2(h10, h11);
                    *(uint32_t*)&hout16[e2] = packh2(h20, h21);
                }
            }
        }
    }
}

// ======================= final head ==========================================
__global__ void final2(const float* __restrict__ skip,
                       const float* __restrict__ Wl1, const float* __restrict__ bl1,
                       const float* __restrict__ Wl2, const float* __restrict__ bl2,
                       float* __restrict__ out) {
    __shared__ float tile[128 * 65];
    __shared__ float b1s[64];
    __shared__ float W2s[64];
    int tid = threadIdx.x;   // 128
    if (tid < 64) { b1s[tid] = bl1[tid]; W2s[tid] = Wl2[tid]; }
    int t0 = (blockIdx.x & 255) * 128;
    int b  = blockIdx.x >> 8;
    for (int i = tid; i < 128 * 64; i += 128) {
        int rr = i >> 6, cc = i & 63;
        tile[rr * 65 + cc] = skip[((size_t)b * TLEN + t0) * 64 + i];
    }
    __syncthreads();
    float s1[64];
    #pragma unroll 8
    for (int j = 0; j < 64; ++j)
        s1[j] = fmaxf(tile[tid * 65 + j] * SQRT_INV_L, 0.f);
    float y2 = bl2[0];
    for (int o = 0; o < 64; ++o) {
        float a = b1s[o];
        #pragma unroll 8
        for (int j = 0; j < 64; ++j) a += Wl1[o * 64 + j] * s1[j];
        y2 += W2s[o] * fmaxf(a, 0.f);
    }
    out[(size_t)b * TLEN + t0 + tid] = y2;
}

// ======================= launch ==============================================
extern "C" void kernel_launch(void* const* d_in, const int* in_sizes, int n_in,
                              void* d_out, int out_size)
{
    const float* x       = (const float*)d_in[0];
    const float* c       = (const float*)d_in[1];
    const float* W_first = (const float*)d_in[2];
    const float* b_first = (const float*)d_in[3];
    const float* W_cin   = (const float*)d_in[4];
    const float* W_up    = (const float*)d_in[5];
    const float* Wd      = (const float*)d_in[6];
    const float* bd      = (const float*)d_in[7];
    const float* Wa      = (const float*)d_in[8];
    const float* Ws      = (const float*)d_in[9];
    const float* bs      = (const float*)d_in[10];
    const float* Wr      = (const float*)d_in[11];
    const float* br      = (const float*)d_in[12];
    const float* Wl1     = (const float*)d_in[13];
    const float* bl1     = (const float*)d_in[14];
    const float* Wl2     = (const float*)d_in[15];
    const float* bl2     = (const float*)d_in[16];
    float* out = (float*)d_out;

    float *skip, *h32a, *h32b;
    __half *h16a, *h16b, *c16, *Wg16, *W216;
    cudaGetSymbolAddress((void**)&skip, g_skip);
    cudaGetSymbolAddress((void**)&h32a, g_h32a);
    cudaGetSymbolAddress((void**)&h32b, g_h32b);
    cudaGetSymbolAddress((void**)&h16a, g_h16a);
    cudaGetSymbolAddress((void**)&h16b, g_h16b);
    cudaGetSymbolAddress((void**)&c16,  g_c16);
    cudaGetSymbolAddress((void**)&Wg16, g_Wg16);
    cudaGetSymbolAddress((void**)&W216, g_W216);

    const int COND_SMEM = (80 * 6 + 80 * 8 + 80 * 8 + 80 * 14 + 80 * 36 + 80 * 128) * 4;
    cudaFuncSetAttribute(cond_fused, cudaFuncAttributeMaxDynamicSharedMemorySize, COND_SMEM);
    cudaFuncSetAttribute(layer_mma, cudaFuncAttributeMaxDynamicSharedMemorySize, SMEM_NEED);

    {
        dim3 grid(TLEN / 128, NB);
        cond_fused<<<grid, 256, COND_SMEM>>>(c, W_cin, W_up, c16);
    }
    {
        int N = NLAYERS * 5 * 128 * 64 + NLAYERS * 128 * 64;
        prepack_w<<<(N + 255) / 256, 256>>>(Wd, Wa, Ws, Wr, Wg16, W216);
    }
    {
        int N = NB * TLEN * RC;
        first_pack<<<(N + 255) / 256, 256>>>(x, W_first, b_first, h32a, h16a, skip);
    }
    float *hi32 = h32a, *ho32 = h32b;
    __half *hi16 = h16a, *ho16 = h16b;
    dim3 grid(TLEN / 128, NB);
    for (int i = 0; i < NLAYERS; ++i) {
        int d = 1 << (i % 10);
        layer_mma<<<grid, 256, SMEM_NEED>>>(i, d, hi32, ho32, hi16, ho16,
                                            c16, skip, Wg16, W216, bd, bs, br);
        { float* t = hi32; hi32 = ho32; ho32 = t; }
        { __half* t = hi16; hi16 = ho16; ho16 = t; }
    }
    final2<<<NB * (TLEN / 128), 128>>>(skip, Wl1, bl1, Wl2, bl2, out);
}

// round 15
// speedup vs baseline: 1.0139x; 1.0139x over previous
#include <cuda_runtime.h>
#include <cuda_fp16.h>
#include <math.h>
#include <stdint.h>

#define TLEN 32768
#define NB 2
#define RC 64
#define GC 128
#define SC 64
#define AC 80
#define NLAYERS 30
#define SQRT_HALF 0.70710678118654752440f
#define SQRT_INV_L 0.18257418583505537115f

// ======================= scratch (device globals) ============================
__device__ float g_h32a[NB * TLEN * RC];                    // fp32 residual carry
__device__ float g_h32b[NB * TLEN * RC];
__device__ __align__(16) __half g_h16a[NB * TLEN * RC];     // fp16 MMA snapshot
__device__ __align__(16) __half g_h16b[NB * TLEN * RC];
__device__ float g_skip[NB * TLEN * SC];
__device__ __align__(16) __half g_c16[NB * 2 * TLEN * 64];
__device__ __align__(16) __half g_Wg16[NLAYERS * 5 * 128 * 64];
__device__ __align__(16) __half g_W216[NLAYERS * 128 * 64];

// ======================= helpers =============================================
__device__ __forceinline__ uint32_t smem_u32(const void* p) {
    uint32_t a;
    asm("{ .reg .u64 t; cvta.to.shared.u64 t, %1; cvt.u32.u64 %0, t; }" : "=r"(a) : "l"(p));
    return a;
}
__device__ __forceinline__ void ldm4(uint32_t* r, uint32_t addr) {
    asm volatile("ldmatrix.sync.aligned.m8n8.x4.shared.b16 {%0,%1,%2,%3}, [%4];"
        : "=r"(r[0]), "=r"(r[1]), "=r"(r[2]), "=r"(r[3]) : "r"(addr));
}
__device__ __forceinline__ void mma16816(float* d, const uint32_t* a, uint32_t b0, uint32_t b1) {
    asm volatile("mma.sync.aligned.m16n8k16.row.col.f32.f16.f16.f32 "
        "{%0,%1,%2,%3}, {%4,%5,%6,%7}, {%8,%9}, {%0,%1,%2,%3};"
        : "+f"(d[0]), "+f"(d[1]), "+f"(d[2]), "+f"(d[3])
        : "r"(a[0]), "r"(a[1]), "r"(a[2]), "r"(a[3]), "r"(b0), "r"(b1));
}
__device__ __forceinline__ void cpa16(uint32_t dst, const void* src, int srcsz) {
    asm volatile("cp.async.ca.shared.global [%0], [%1], 16, %2;"
        :: "r"(dst), "l"(src), "r"(srcsz) : "memory");
}
#define CP_COMMIT() asm volatile("cp.async.commit_group;" ::: "memory")
#define CP_WAIT0()  asm volatile("cp.async.wait_group 0;" ::: "memory")
#define CP_WAIT1()  asm volatile("cp.async.wait_group 1;" ::: "memory")

__device__ __forceinline__ uint32_t packh2(float lo, float hi) {
    __half2 t = __floats2half2_rn(lo, hi);
    return *(uint32_t*)&t;
}

// ======================= fused conditioning ==================================
__global__ void cond_fused(const float* __restrict__ c, const float* __restrict__ Wc,
                           const float* __restrict__ Wup,
                           __half* __restrict__ P16) {
    extern __shared__ float us[];
    const int b  = blockIdx.y;
    const int t0 = blockIdx.x * 128;
    const int tid = threadIdx.x;   // 256

    const int u0 = (t0 - 4) >> 2;
    const int un = ((t0 + 131) >> 2) - u0 + 1;
    const int v0 = (u0 - 4) >> 2;
    const int vn = ((u0 + un - 1 + 4) >> 2) - v0 + 1;
    const int w0 = (v0 - 4) >> 2;
    const int wn = ((v0 + vn - 1 + 4) >> 2) - w0 + 1;
    const int f0 = (w0 - 4) >> 2;
    const int fn = ((w0 + wn - 1 + 4) >> 2) - f0 + 1;

    float* y0 = us;
    float* y1 = y0 + 80 * 6;
    float* s1 = y1 + 80 * 8;
    float* s2 = s1 + 80 * 8;
    float* s3 = s2 + 80 * 14;
    float* s4 = s3 + 80 * 36;

    for (int i = tid; i < 80 * fn; i += 256) {
        int ch = i / fn, ff = i - ch * fn;
        int f = f0 + ff;
        y0[ch * 6 + ff] = (f >= 0 && f < 128) ? c[((size_t)b * 80 + ch) * 128 + f] : 0.f;
    }
    __syncthreads();
    for (int i = tid; i < 80 * fn; i += 256) {
        int o = i / fn, ff = i - o * fn;
        float acc = 0.f;
        #pragma unroll 4
        for (int k = 0; k < 80; ++k) acc += Wc[o * 80 + k] * y0[k * 6 + ff];
        y1[o * 8 + ff] = acc;
    }
    __syncthreads();
    for (int i = tid; i < 80 * wn; i += 256) {
        int o = i / wn, wi = i - o * wn;
        int w = w0 + wi;
        float acc = 0.f;
        #pragma unroll
        for (int k = 0; k < 9; ++k) {
            int rr = w - 4 + k;
            if (rr >= 0 && rr < 512) acc += Wup[k] * y1[o * 8 + ((rr >> 2) - f0)];
        }
        s1[o * 8 + wi] = acc;
    }
    __syncthreads();
    for (int i = tid; i < 80 * vn; i += 256) {
        int o = i / vn, vi = i - o * vn;
        int v = v0 + vi;
        float acc = 0.f;
        #pragma unroll
        for (int k = 0; k < 9; ++k) {
            int rr = v - 4 + k;
            if (rr >= 0 && rr < 2048) acc += Wup[9 + k] * s1[o * 8 + ((rr >> 2) - w0)];
        }
        s2[o * 14 + vi] = acc;
    }
    __syncthreads();
    for (int i = tid; i < 80 * un; i += 256) {
        int o = i / un, ui = i - o * un;
        int u = u0 + ui;
        float acc = 0.f;
        #pragma unroll
        for (int k = 0; k < 9; ++k) {
            int rr = u - 4 + k;
            if (rr >= 0 && rr < 8192) acc += Wup[18 + k] * s2[o * 14 + ((rr >> 2) - v0)];
        }
        s3[o * 36 + ui] = acc;
    }
    __syncthreads();
    for (int i = tid; i < 80 * 128; i += 256) {
        int o = i >> 7, tl = i & 127;
        int t = t0 + tl;
        float acc = 0.f;
        #pragma unroll
        for (int k = 0; k < 9; ++k) {
            int rr = t - 4 + k;
            if (rr >= 0 && rr < TLEN) acc += Wup[27 + k] * s3[o * 36 + ((rr >> 2) - u0)];
        }
        s4[o * 128 + tl] = acc;
    }
    __syncthreads();
    for (int i = tid; i < 128 * 64; i += 256) {
        int tl = i >> 6, j = i & 63;
        size_t o0 = (((size_t)b * 2 + 0) * TLEN + (t0 + tl)) * 64 + j;
        size_t o1 = (((size_t)b * 2 + 1) * TLEN + (t0 + tl)) * 64 + j;
        float v0f = s4[j * 128 + tl];
        float v1f = (j < 16) ? s4[(64 + j) * 128 + tl] : 0.f;
        P16[o0] = __float2half(v0f);
        P16[o1] = __float2half(v1f);
    }
}

// ======================= weight prepack ======================================
__global__ void prepack_w(const float* __restrict__ Wd, const float* __restrict__ Wa,
                          const float* __restrict__ Ws, const float* __restrict__ Wr,
                          __half* __restrict__ Wg16, __half* __restrict__ W216) {
    const int N1 = NLAYERS * 5 * 128 * 64;
    const int N2 = NLAYERS * 128 * 64;
    int i = blockIdx.x * blockDim.x + threadIdx.x;
    if (i < N1) {
        int kl = i & 63;
        int r  = (i >> 6) & 127;
        int lc = i >> 13;
        int cc = lc % 5;
        int l  = lc / 5;
        int j  = ((r >> 4) << 3) + (((r & 7) >> 1) << 1) + ((r >> 3) & 1);
        int ch = (r & 1) ? (64 + j) : j;
        float w;
        if (cc < 3)       w = Wd[(((size_t)l * GC + ch) * RC + kl) * 3 + cc];
        else if (cc == 3) w = Wa[((size_t)l * GC + ch) * AC + kl];
        else              w = (kl < AC - 64) ? Wa[((size_t)l * GC + ch) * AC + 64 + kl] : 0.f;
        Wg16[i] = __float2half(w);
    } else if (i - N1 < N2) {
        int i2 = i - N1;
        int k  = i2 & 63;
        int r2 = (i2 >> 6) & 127;
        int l  = i2 >> 13;
        float w = (r2 < 64) ? Ws[((size_t)l * SC + r2) * 64 + k]
                            : Wr[((size_t)l * RC + (r2 - 64)) * 64 + k];
        W216[i2] = __float2half(w);
    }
}

__global__ void first_pack(const float* __restrict__ x,
                           const float* __restrict__ Wf, const float* __restrict__ bf,
                           float* __restrict__ h32, __half* __restrict__ h16,
                           float* __restrict__ skip) {
    int idx = blockIdx.x * blockDim.x + threadIdx.x;
    if (idx >= NB * TLEN * RC) return;
    int j = idx & 63;
    int t = (idx >> 6) & (TLEN - 1);
    int b = idx >> 21;
    float v = Wf[j] * x[(size_t)b * TLEN + t] + bf[j];
    h32[idx] = v;
    h16[idx] = __float2half(v);
    skip[idx] = 0.f;
}

// ======================= fused residual layer ================================
// 128-t tile, 8 warps m32n64; W double buffer + contiguous 256-row D region.
#define STRIDE 144
#define RSZ (128 * STRIDE)
#define OFF_W0  0
#define OFF_D0  (2 * RSZ)
#define OFF_BD  (4 * RSZ)
#define SMEM_NEED (OFF_BD + 1024)

__global__ __launch_bounds__(256, 2)
void layer_mma(int l, int dil,
               const float* __restrict__ hin32, float* __restrict__ hout32,
               const __half* __restrict__ hin16, __half* __restrict__ hout16,
               const __half* __restrict__ c16,
               float* __restrict__ skip,
               const __half* __restrict__ Wg16, const __half* __restrict__ W216,
               const float* __restrict__ bd, const float* __restrict__ bs,
               const float* __restrict__ br) {
    extern __shared__ char smem_c[];
    const uint32_t sb = smem_u32(smem_c);
    float* sbd = (float*)(smem_c + OFF_BD);

    const int tid  = threadIdx.x;
    const int warp = tid >> 5;
    const int lane = tid & 31;
    const int b    = blockIdx.y;
    const int t0   = blockIdx.x * 128;

    const int wm    = warp & 3;       // t-tile (32 rows)
    const int wn    = warp >> 2;      // n-tile (64 cols)
    const int mbase = wm * 32;
    const int nbase = wn * 64;

    const int lrow  = lane & 15;
    const int lkoff = (lane >> 4) * 16;
    const int q     = lane & 3;
    const int r     = lane >> 2;

    // biases: bd[0..127], bs[128..191], br[192..255]
    if (tid < 128)      sbd[tid] = bd[l * GC + tid];
    else if (tid < 192) sbd[tid] = bs[l * SC + tid - 128];
    else                sbd[tid] = br[l * RC + tid - 192];

    // ---- staging helpers ----
    auto stage_W = [&](int chunk, int buf) {
        const char* wb = (const char*)(Wg16 + (((size_t)l * 5 + chunk) * 128) * 64);
        #pragma unroll
        for (int it = 0; it < 4; ++it) {
            const int p = it * 256 + tid;
            const int row = p >> 3, j = p & 7;
            if (chunk == 4 && j >= 2) continue;
            cpa16(sb + OFF_W0 + buf * RSZ + (uint32_t)row * STRIDE + j * 16, wb + p * 16, 16);
        }
    };
    auto stage_condD = [&](int cc, int dreg) {
        #pragma unroll
        for (int it = 0; it < 4; ++it) {
            const int p = it * 256 + tid;
            const int row = p >> 3, j = p & 7;
            if (cc == 1 && j >= 2) continue;
            const char* src = (const char*)c16
                + (((size_t)b * 2 + cc) * TLEN + (t0 + row)) * 128 + j * 16;
            cpa16(sb + OFF_D0 + dreg * RSZ + (uint32_t)row * STRIDE + j * 16, src, 16);
        }
    };
    auto stage_DU = [&](int g0, int nrows) {
        for (int p = tid; p < nrows * 8; p += 256) {
            const int g = g0 + (p >> 3), j = p & 7;
            const int t = t0 - dil + g;
            const char* src; int sz = 16;
            if (t >= 0 && t < TLEN)
                src = (const char*)hin16 + ((size_t)b * TLEN + t) * 128 + j * 16;
            else { src = (const char*)hin16; sz = 0; }
            cpa16(sb + OFF_D0 + (uint32_t)g * STRIDE + j * 16, src, sz);
        }
    };
    auto stage_tapD = [&](int c, int buf) {
        #pragma unroll
        for (int it = 0; it < 4; ++it) {
            const int p = it * 256 + tid;
            const int row = p >> 3, j = p & 7;
            const char* src; int sz = 16;
            int tg = t0 + row + (c - 1) * dil;
            if (tg >= 0 && tg < TLEN)
                src = (const char*)hin16 + ((size_t)b * TLEN + tg) * 128 + j * 16;
            else { src = (const char*)hin16; sz = 0; }
            cpa16(sb + OFF_D0 + buf * RSZ + (uint32_t)row * STRIDE + j * 16, src, sz);
        }
    };
    auto stage_w2 = [&](int buf) {
        const char* wb = (const char*)(W216 + (size_t)l * 128 * 64);
        #pragma unroll
        for (int it = 0; it < 4; ++it) {
            const int p = it * 256 + tid;
            const int row = p >> 3, j = p & 7;
            cpa16(sb + OFF_W0 + buf * RSZ + (uint32_t)row * STRIDE + j * 16, wb + p * 16, 16);
        }
    };

    float acc[16][4];
    #pragma unroll
    for (int i = 0; i < 16; ++i)
        #pragma unroll
        for (int j2 = 0; j2 < 4; ++j2) acc[i][j2] = 0.f;

    auto do_mma = [&](uint32_t abase, uint32_t wbase, int nks) {
        for (int ks = 0; ks < nks; ++ks) {
            uint32_t a0f[4], a1f[4];
            ldm4(a0f, abase + ks * 32);
            ldm4(a1f, abase + 16 * STRIDE + ks * 32);
            uint32_t bf4[4][4];
            #pragma unroll
            for (int i = 0; i < 4; ++i)
                ldm4(bf4[i], wbase + (uint32_t)(nbase + i * 16 + lrow) * STRIDE + lkoff + ks * 32);
            #pragma unroll
            for (int i = 0; i < 4; ++i) {
                mma16816(acc[i * 2],         a0f, bf4[i][0], bf4[i][2]);
                mma16816(acc[i * 2 + 1],     a0f, bf4[i][1], bf4[i][3]);
            }
            #pragma unroll
            for (int i = 0; i < 4; ++i) {
                mma16816(acc[8 + i * 2],     a1f, bf4[i][0], bf4[i][2]);
                mma16816(acc[8 + i * 2 + 1], a1f, bf4[i][1], bf4[i][3]);
            }
        }
    };

    const uint32_t arow = (uint32_t)(mbase + lrow);
    uint32_t zoff;

    if (dil <= 64) {
        // ======== path A: cond first, then union taps (R13 schedule) ========
        stage_W(3, 0); stage_condD(0, 0); CP_COMMIT();   // G1
        stage_W(4, 1); stage_condD(1, 1); CP_COMMIT();   // G2
        // p0: cond lo
        CP_WAIT1(); __syncthreads();
        do_mma(sb + OFF_D0 + arow * STRIDE + lkoff, sb + OFF_W0, 4);
        __syncthreads();
        stage_W(0, 0); stage_DU(0, 128); CP_COMMIT();    // G3
        // p1: cond hi (16k)
        CP_WAIT1(); __syncthreads();
        do_mma(sb + OFF_D0 + RSZ + arow * STRIDE + lkoff, sb + OFF_W0 + RSZ, 1);
        __syncthreads();
        stage_W(1, 1); stage_DU(128, 2 * dil); CP_COMMIT(); // G4
        // p2: tap0
        CP_WAIT1(); __syncthreads();
        do_mma(sb + OFF_D0 + arow * STRIDE + lkoff, sb + OFF_W0, 4);
        __syncthreads();
        stage_W(2, 0); CP_COMMIT();                      // G5
        // p3: tap1
        CP_WAIT1(); __syncthreads();
        do_mma(sb + OFF_D0 + (arow + dil) * STRIDE + lkoff, sb + OFF_W0 + RSZ, 4);
        __syncthreads();
        stage_w2(1); CP_COMMIT();                        // G6
        // p4: tap2
        CP_WAIT1(); __syncthreads();
        do_mma(sb + OFF_D0 + (arow + 2 * dil) * STRIDE + lkoff, sb + OFF_W0, 4);
        __syncthreads();
        zoff = OFF_D0;
    } else {
        // ======== path B: per-tap pipeline ========
        stage_W(0, 0); stage_tapD(0, 0); CP_COMMIT();
        stage_W(1, 1); stage_tapD(1, 1); CP_COMMIT();
        for (int c = 0; c < 5; ++c) {
            CP_WAIT1(); __syncthreads();
            const int buf = c & 1;
            do_mma(sb + OFF_D0 + buf * RSZ + arow * STRIDE + lkoff,
                   sb + OFF_W0 + buf * RSZ, (c == 4) ? 1 : 4);
            __syncthreads();
            if (c < 3) {
                const int nc = c + 2, nbuf = nc & 1;
                stage_W(nc, nbuf);
                if (nc < 3) stage_tapD(nc, nbuf);
                else        stage_condD(nc - 3, nbuf);
                CP_COMMIT();
            } else if (c == 3) { stage_w2(1); CP_COMMIT(); }
        }
        zoff = OFF_D0 + RSZ;
    }

    // ---------------- gate -> z (fp16), single-divide form --------------------
    #pragma unroll
    for (int mf = 0; mf < 2; ++mf) {
        const int tr0 = mbase + mf * 16 + r;
        #pragma unroll
        for (int i = 0; i < 4; ++i) {
            #pragma unroll
            for (int p = 0; p < 2; ++p) {
                const int j = (wn * 4 + i) * 8 + 2 * q + p;
                const float ba = sbd[j], bb = sbd[64 + j];
                const float* a = acc[(mf * 4 + i) * 2 + p];
                #pragma unroll
                for (int h = 0; h < 2; ++h) {
                    float xa = a[h * 2 + 0] + ba;
                    float xb = a[h * 2 + 1] + bb;
                    float e2a = __expf(-2.f * fabsf(xa));
                    float e2b = __expf(-xb);
                    float num = copysignf(1.f - e2a, xa);
                    float z   = __fdividef(num, (1.f + e2a) * (1.f + e2b));
                    const int tr = tr0 + h * 8;
                    *(__half*)(smem_c + zoff + (uint32_t)tr * STRIDE + j * 2) = __float2half(z);
                }
            }
        }
    }

    CP_WAIT0();
    __syncthreads();

    // ---------------- GEMM2: z * W2^T (W buf1) ----------------
    float acc2[16][4];
    #pragma unroll
    for (int i = 0; i < 16; ++i)
        #pragma unroll
        for (int j2 = 0; j2 < 4; ++j2) acc2[i][j2] = 0.f;

    #pragma unroll
    for (int ks = 0; ks < 4; ++ks) {
        uint32_t a0f[4], a1f[4];
        const uint32_t a0 = sb + zoff + arow * STRIDE + lkoff + ks * 32;
        ldm4(a0f, a0);
        ldm4(a1f, a0 + 16 * STRIDE);
        uint32_t wf4[4][4];
        #pragma unroll
        for (int i = 0; i < 4; ++i)
            ldm4(wf4[i], sb + OFF_W0 + RSZ + (uint32_t)(nbase + i * 16 + lrow) * STRIDE + lkoff + ks * 32);
        #pragma unroll
        for (int i = 0; i < 4; ++i) {
            mma16816(acc2[i * 2],         a0f, wf4[i][0], wf4[i][2]);
            mma16816(acc2[i * 2 + 1],     a0f, wf4[i][1], wf4[i][3]);
        }
        #pragma unroll
        for (int i = 0; i < 4; ++i) {
            mma16816(acc2[8 + i * 2],     a1f, wf4[i][0], wf4[i][2]);
            mma16816(acc2[8 + i * 2 + 1], a1f, wf4[i][1], wf4[i][3]);
        }
    }

    // ---------------- epilogue (warp-uniform, coalesced [t][ch]) -------------
    if (wn == 0) {                         // out-ch 0..63 -> skip
        #pragma unroll
        for (int mf = 0; mf < 2; ++mf) {
            const int trowA = t0 + mbase + mf * 16 + r;
            const int trowB = trowA + 8;
            #pragma unroll
            for (int i = 0; i < 4; ++i) {
                #pragma unroll
                for (int p = 0; p < 2; ++p) {
                    const int ch = i * 16 + p * 8 + 2 * q;
                    const float* d = acc2[(mf * 4 + i) * 2 + p];
                    float bs0 = sbd[128 + ch], bs1 = sbd[128 + ch + 1];
                    float2* p1 = (float2*)&skip[((size_t)b * TLEN + trowA) * 64 + ch];
                    float2* p2 = (float2*)&skip[((size_t)b * TLEN + trowB) * 64 + ch];
                    float2 v1 = *p1, v2 = *p2;
                    v1.x += d[0] + bs0; v1.y += d[1] + bs1;
                    v2.x += d[2] + bs0; v2.y += d[3] + bs1;
                    *p1 = v1; *p2 = v2;
                }
            }
        }
    } else {                               // out-ch 64..127 -> residual
        #pragma unroll
        for (int mf = 0; mf < 2; ++mf) {
            const int trowA = t0 + mbase + mf * 16 + r;
            const int trowB = trowA + 8;
            #pragma unroll
            for (int i = 0; i < 4; ++i) {
                #pragma unroll
                for (int p = 0; p < 2; ++p) {
                    const int ch = i * 16 + p * 8 + 2 * q;
                    const float* d = acc2[(mf * 4 + i) * 2 + p];
                    float br0 = sbd[192 + ch], br1 = sbd[192 + ch + 1];
                    size_t e1 = ((size_t)b * TLEN + trowA) * 64 + ch;
                    size_t e2 = ((size_t)b * TLEN + trowB) * 64 + ch;
                    float2 i1 = *(const float2*)&hin32[e1];
                    float2 i2 = *(const float2*)&hin32[e2];
                    float h10 = (d[0] + br0 + i1.x) * SQRT_HALF;
                    float h11 = (d[1] + br1 + i1.y) * SQRT_HALF;
                    float h20 = (d[2] + br0 + i2.x) * SQRT_HALF;
                    float h21 = (d[3] + br1 + i2.y) * SQRT_HALF;
                    *(float2*)&hout32[e1] = make_float2(h10, h11);
                    *(float2*)&hout32[e2] = make_float2(h20, h21);
                    *(uint32_t*)&hout16[e1] = packh2(h10, h11);
                    *(uint32_t*)&hout16[e2] = packh2(h20, h21);
                }
            }
        }
    }
}

// ======================= final head ==========================================
__global__ void final2(const float* __restrict__ skip,
                       const float* __restrict__ Wl1, const float* __restrict__ bl1,
                       const float* __restrict__ Wl2, const float* __restrict__ bl2,
                       float* __restrict__ out) {
    __shared__ float tile[128 * 65];
    __shared__ float b1s[64];
    __shared__ float W2s[64];
    int tid = threadIdx.x;   // 128
    if (tid < 64) { b1s[tid] = bl1[tid]; W2s[tid] = Wl2[tid]; }
    int t0 = (blockIdx.x & 255) * 128;
    int b  = blockIdx.x >> 8;
    for (int i = tid; i < 128 * 64; i += 128) {
        int rr = i >> 6, cc = i & 63;
        tile[rr * 65 + cc] = skip[((size_t)b * TLEN + t0) * 64 + i];
    }
    __syncthreads();
    float s1[64];
    #pragma unroll 8
    for (int j = 0; j < 64; ++j)
        s1[j] = fmaxf(tile[tid * 65 + j] * SQRT_INV_L, 0.f);
    float y2 = bl2[0];
    for (int o = 0; o < 64; ++o) {
        float a = b1s[o];
        #pragma unroll 8
        for (int j = 0; j < 64; ++j) a += Wl1[o * 64 + j] * s1[j];
        y2 += W2s[o] * fmaxf(a, 0.f);
    }
    out[(size_t)b * TLEN + t0 + tid] = y2;
}

// ======================= launch ==============================================
extern "C" void kernel_launch(void* const* d_in, const int* in_sizes, int n_in,
                              void* d_out, int out_size)
{
    const float* x       = (const float*)d_in[0];
    const float* c       = (const float*)d_in[1];
    const float* W_first = (const float*)d_in[2];
    const float* b_first = (const float*)d_in[3];
    const float* W_cin   = (const float*)d_in[4];
    const float* W_up    = (const float*)d_in[5];
    const float* Wd      = (const float*)d_in[6];
    const float* bd      = (const float*)d_in[7];
    const float* Wa      = (const float*)d_in[8];
    const float* Ws      = (const float*)d_in[9];
    const float* bs      = (const float*)d_in[10];
    const float* Wr      = (const float*)d_in[11];
    const float* br      = (const float*)d_in[12];
    const float* Wl1     = (const float*)d_in[13];
    const float* bl1     = (const float*)d_in[14];
    const float* Wl2     = (const float*)d_in[15];
    const float* bl2     = (const float*)d_in[16];
    float* out = (float*)d_out;

    float *skip, *h32a, *h32b;
    __half *h16a, *h16b, *c16, *Wg16, *W216;
    cudaGetSymbolAddress((void**)&skip, g_skip);
    cudaGetSymbolAddress((void**)&h32a, g_h32a);
    cudaGetSymbolAddress((void**)&h32b, g_h32b);
    cudaGetSymbolAddress((void**)&h16a, g_h16a);
    cudaGetSymbolAddress((void**)&h16b, g_h16b);
    cudaGetSymbolAddress((void**)&c16,  g_c16);
    cudaGetSymbolAddress((void**)&Wg16, g_Wg16);
    cudaGetSymbolAddress((void**)&W216, g_W216);

    const int COND_SMEM = (80 * 6 + 80 * 8 + 80 * 8 + 80 * 14 + 80 * 36 + 80 * 128) * 4;
    cudaFuncSetAttribute(cond_fused, cudaFuncAttributeMaxDynamicSharedMemorySize, COND_SMEM);
    cudaFuncSetAttribute(layer_mma, cudaFuncAttributeMaxDynamicSharedMemorySize, SMEM_NEED);

    {
        dim3 grid(TLEN / 128, NB);
        cond_fused<<<grid, 256, COND_SMEM>>>(c, W_cin, W_up, c16);
    }
    {
        int N = NLAYERS * 5 * 128 * 64 + NLAYERS * 128 * 64;
        prepack_w<<<(N + 255) / 256, 256>>>(Wd, Wa, Ws, Wr, Wg16, W216);
    }
    {
        int N = NB * TLEN * RC;
        first_pack<<<(N + 255) / 256, 256>>>(x, W_first, b_first, h32a, h16a, skip);
    }
    float *hi32 = h32a, *ho32 = h32b;
    __half *hi16 = h16a, *ho16 = h16b;
    dim3 grid(TLEN / 128, NB);
    for (int i = 0; i < NLAYERS; ++i) {
        int d = 1 << (i % 10);
        layer_mma<<<grid, 256, SMEM_NEED>>>(i, d, hi32, ho32, hi16, ho16,
                                            c16, skip, Wg16, W216, bd, bs, br);
        { float* t = hi32; hi32 = ho32; ho32 = t; }
        { __half* t = hi16; hi16 = ho16; ho16 = t; }
    }
    final2<<<NB * (TLEN / 128), 128>>>(skip, Wl1, bl1, Wl2, bl2, out);
}

// round 16
// speedup vs baseline: 1.0313x; 1.0172x over previous
#include <cuda_runtime.h>
#include <cuda_fp16.h>
#include <math.h>
#include <stdint.h>

#define TLEN 32768
#define NB 2
#define RC 64
#define GC 128
#define SC 64
#define AC 80
#define NLAYERS 30
#define SQRT_HALF 0.70710678118654752440f
#define SQRT_INV_L 0.18257418583505537115f

// ======================= scratch (device globals) ============================
__device__ float g_h32a[NB * TLEN * RC];                    // fp32 residual carry
__device__ float g_h32b[NB * TLEN * RC];
__device__ __align__(16) __half g_h16a[NB * TLEN * RC];     // fp16 MMA snapshot
__device__ __align__(16) __half g_h16b[NB * TLEN * RC];
__device__ float g_skip[NB * TLEN * SC];
__device__ __align__(16) __half g_c16[NB * 2 * TLEN * 64];
__device__ __align__(16) __half g_Wg16[NLAYERS * 5 * 128 * 64];
__device__ __align__(16) __half g_W216[NLAYERS * 128 * 64];

// ======================= helpers =============================================
__device__ __forceinline__ uint32_t smem_u32(const void* p) {
    uint32_t a;
    asm("{ .reg .u64 t; cvta.to.shared.u64 t, %1; cvt.u32.u64 %0, t; }" : "=r"(a) : "l"(p));
    return a;
}
__device__ __forceinline__ void ldm4(uint32_t* r, uint32_t addr) {
    asm volatile("ldmatrix.sync.aligned.m8n8.x4.shared.b16 {%0,%1,%2,%3}, [%4];"
        : "=r"(r[0]), "=r"(r[1]), "=r"(r[2]), "=r"(r[3]) : "r"(addr));
}
__device__ __forceinline__ void mma16816(float* d, const uint32_t* a, uint32_t b0, uint32_t b1) {
    asm volatile("mma.sync.aligned.m16n8k16.row.col.f32.f16.f16.f32 "
        "{%0,%1,%2,%3}, {%4,%5,%6,%7}, {%8,%9}, {%0,%1,%2,%3};"
        : "+f"(d[0]), "+f"(d[1]), "+f"(d[2]), "+f"(d[3])
        : "r"(a[0]), "r"(a[1]), "r"(a[2]), "r"(a[3]), "r"(b0), "r"(b1));
}
__device__ __forceinline__ void cpa16(uint32_t dst, const void* src, int srcsz) {
    asm volatile("cp.async.ca.shared.global [%0], [%1], 16, %2;"
        :: "r"(dst), "l"(src), "r"(srcsz) : "memory");
}
#define CP_COMMIT() asm volatile("cp.async.commit_group;" ::: "memory")
#define CP_WAIT0()  asm volatile("cp.async.wait_group 0;" ::: "memory")
#define CP_WAIT1()  asm volatile("cp.async.wait_group 1;" ::: "memory")

__device__ __forceinline__ uint32_t packh2(float lo, float hi) {
    __half2 t = __floats2half2_rn(lo, hi);
    return *(uint32_t*)&t;
}

// ======================= fused conditioning ==================================
__global__ void cond_fused(const float* __restrict__ c, const float* __restrict__ Wc,
                           const float* __restrict__ Wup,
                           __half* __restrict__ P16) {
    extern __shared__ float us[];
    const int b  = blockIdx.y;
    const int t0 = blockIdx.x * 128;
    const int tid = threadIdx.x;   // 256

    const int u0 = (t0 - 4) >> 2;
    const int un = ((t0 + 131) >> 2) - u0 + 1;
    const int v0 = (u0 - 4) >> 2;
    const int vn = ((u0 + un - 1 + 4) >> 2) - v0 + 1;
    const int w0 = (v0 - 4) >> 2;
    const int wn = ((v0 + vn - 1 + 4) >> 2) - w0 + 1;
    const int f0 = (w0 - 4) >> 2;
    const int fn = ((w0 + wn - 1 + 4) >> 2) - f0 + 1;

    float* y0 = us;
    float* y1 = y0 + 80 * 6;
    float* s1 = y1 + 80 * 8;
    float* s2 = s1 + 80 * 8;
    float* s3 = s2 + 80 * 14;
    float* s4 = s3 + 80 * 36;

    for (int i = tid; i < 80 * fn; i += 256) {
        int ch = i / fn, ff = i - ch * fn;
        int f = f0 + ff;
        y0[ch * 6 + ff] = (f >= 0 && f < 128) ? c[((size_t)b * 80 + ch) * 128 + f] : 0.f;
    }
    __syncthreads();
    for (int i = tid; i < 80 * fn; i += 256) {
        int o = i / fn, ff = i - o * fn;
        float acc = 0.f;
        #pragma unroll 4
        for (int k = 0; k < 80; ++k) acc += Wc[o * 80 + k] * y0[k * 6 + ff];
        y1[o * 8 + ff] = acc;
    }
    __syncthreads();
    for (int i = tid; i < 80 * wn; i += 256) {
        int o = i / wn, wi = i - o * wn;
        int w = w0 + wi;
        float acc = 0.f;
        #pragma unroll
        for (int k = 0; k < 9; ++k) {
            int rr = w - 4 + k;
            if (rr >= 0 && rr < 512) acc += Wup[k] * y1[o * 8 + ((rr >> 2) - f0)];
        }
        s1[o * 8 + wi] = acc;
    }
    __syncthreads();
    for (int i = tid; i < 80 * vn; i += 256) {
        int o = i / vn, vi = i - o * vn;
        int v = v0 + vi;
        float acc = 0.f;
        #pragma unroll
        for (int k = 0; k < 9; ++k) {
            int rr = v - 4 + k;
            if (rr >= 0 && rr < 2048) acc += Wup[9 + k] * s1[o * 8 + ((rr >> 2) - w0)];
        }
        s2[o * 14 + vi] = acc;
    }
    __syncthreads();
    for (int i = tid; i < 80 * un; i += 256) {
        int o = i / un, ui = i - o * un;
        int u = u0 + ui;
        float acc = 0.f;
        #pragma unroll
        for (int k = 0; k < 9; ++k) {
            int rr = u - 4 + k;
            if (rr >= 0 && rr < 8192) acc += Wup[18 + k] * s2[o * 14 + ((rr >> 2) - v0)];
        }
        s3[o * 36 + ui] = acc;
    }
    __syncthreads();
    for (int i = tid; i < 80 * 128; i += 256) {
        int o = i >> 7, tl = i & 127;
        int t = t0 + tl;
        float acc = 0.f;
        #pragma unroll
        for (int k = 0; k < 9; ++k) {
            int rr = t - 4 + k;
            if (rr >= 0 && rr < TLEN) acc += Wup[27 + k] * s3[o * 36 + ((rr >> 2) - u0)];
        }
        s4[o * 128 + tl] = acc;
    }
    __syncthreads();
    for (int i = tid; i < 128 * 64; i += 256) {
        int tl = i >> 6, j = i & 63;
        size_t o0 = (((size_t)b * 2 + 0) * TLEN + (t0 + tl)) * 64 + j;
        size_t o1 = (((size_t)b * 2 + 1) * TLEN + (t0 + tl)) * 64 + j;
        float v0f = s4[j * 128 + tl];
        float v1f = (j < 16) ? s4[(64 + j) * 128 + tl] : 0.f;
        P16[o0] = __float2half(v0f);
        P16[o1] = __float2half(v1f);
    }
}

// ======================= weight prepack ======================================
__global__ void prepack_w(const float* __restrict__ Wd, const float* __restrict__ Wa,
                          const float* __restrict__ Ws, const float* __restrict__ Wr,
                          __half* __restrict__ Wg16, __half* __restrict__ W216) {
    const int N1 = NLAYERS * 5 * 128 * 64;
    const int N2 = NLAYERS * 128 * 64;
    int i = blockIdx.x * blockDim.x + threadIdx.x;
    if (i < N1) {
        int kl = i & 63;
        int r  = (i >> 6) & 127;
        int lc = i >> 13;
        int cc = lc % 5;
        int l  = lc / 5;
        int j  = ((r >> 4) << 3) + (((r & 7) >> 1) << 1) + ((r >> 3) & 1);
        int ch = (r & 1) ? (64 + j) : j;
        float w;
        if (cc < 3)       w = Wd[(((size_t)l * GC + ch) * RC + kl) * 3 + cc];
        else if (cc == 3) w = Wa[((size_t)l * GC + ch) * AC + kl];
        else              w = (kl < AC - 64) ? Wa[((size_t)l * GC + ch) * AC + 64 + kl] : 0.f;
        Wg16[i] = __float2half(w);
    } else if (i - N1 < N2) {
        int i2 = i - N1;
        int k  = i2 & 63;
        int r2 = (i2 >> 6) & 127;
        int l  = i2 >> 13;
        float w = (r2 < 64) ? Ws[((size_t)l * SC + r2) * 64 + k]
                            : Wr[((size_t)l * RC + (r2 - 64)) * 64 + k];
        W216[i2] = __float2half(w);
    }
}

__global__ void first_pack(const float* __restrict__ x,
                           const float* __restrict__ Wf, const float* __restrict__ bf,
                           float* __restrict__ h32, __half* __restrict__ h16,
                           float* __restrict__ skip) {
    int idx = blockIdx.x * blockDim.x + threadIdx.x;
    if (idx >= NB * TLEN * RC) return;
    int j = idx & 63;
    int t = (idx >> 6) & (TLEN - 1);
    int b = idx >> 21;
    float v = Wf[j] * x[(size_t)b * TLEN + t] + bf[j];
    h32[idx] = v;
    h16[idx] = __float2half(v);
    skip[idx] = 0.f;
}

// ======================= fused residual layer ================================
// 128-t tile, 8 warps m32n64; W double buffer + contiguous 256-row D region.
#define STRIDE 144
#define RSZ (128 * STRIDE)
#define OFF_W0  0
#define OFF_D0  (2 * RSZ)
#define OFF_BD  (4 * RSZ)
#define SMEM_NEED (OFF_BD + 1024)

__global__ __launch_bounds__(256, 2)
void layer_mma(int l, int dil,
               const float* __restrict__ hin32, float* __restrict__ hout32,
               const __half* __restrict__ hin16, __half* __restrict__ hout16,
               const __half* __restrict__ c16,
               float* __restrict__ skip,
               const __half* __restrict__ Wg16, const __half* __restrict__ W216,
               const float* __restrict__ bd, const float* __restrict__ bs,
               const float* __restrict__ br) {
    extern __shared__ char smem_c[];
    const uint32_t sb = smem_u32(smem_c);
    float* sbd = (float*)(smem_c + OFF_BD);

    const int tid  = threadIdx.x;
    const int warp = tid >> 5;
    const int lane = tid & 31;
    const int b    = blockIdx.y;
    const int t0   = blockIdx.x * 128;

    const int wm    = warp & 3;       // t-tile (32 rows)
    const int wn    = warp >> 2;      // n-tile (64 cols)
    const int mbase = wm * 32;
    const int nbase = wn * 64;

    const int lrow  = lane & 15;
    const int lkoff = (lane >> 4) * 16;
    const int q     = lane & 3;
    const int r     = lane >> 2;

    // biases: bd[0..127], bs[128..191], br[192..255]
    if (tid < 128)      sbd[tid] = bd[l * GC + tid];
    else if (tid < 192) sbd[tid] = bs[l * SC + tid - 128];
    else                sbd[tid] = br[l * RC + tid - 192];

    // ---- staging helpers ----
    auto stage_W = [&](int chunk, int buf) {
        const char* wb = (const char*)(Wg16 + (((size_t)l * 5 + chunk) * 128) * 64);
        #pragma unroll
        for (int it = 0; it < 4; ++it) {
            const int p = it * 256 + tid;
            const int row = p >> 3, j = p & 7;
            if (chunk == 4 && j >= 2) continue;
            cpa16(sb + OFF_W0 + buf * RSZ + (uint32_t)row * STRIDE + j * 16, wb + p * 16, 16);
        }
    };
    auto stage_condD = [&](int cc, int dreg) {
        #pragma unroll
        for (int it = 0; it < 4; ++it) {
            const int p = it * 256 + tid;
            const int row = p >> 3, j = p & 7;
            if (cc == 1 && j >= 2) continue;
            const char* src = (const char*)c16
                + (((size_t)b * 2 + cc) * TLEN + (t0 + row)) * 128 + j * 16;
            cpa16(sb + OFF_D0 + dreg * RSZ + (uint32_t)row * STRIDE + j * 16, src, 16);
        }
    };
    auto stage_DU = [&](int g0, int nrows) {
        for (int p = tid; p < nrows * 8; p += 256) {
            const int g = g0 + (p >> 3), j = p & 7;
            const int t = t0 - dil + g;
            const char* src; int sz = 16;
            if (t >= 0 && t < TLEN)
                src = (const char*)hin16 + ((size_t)b * TLEN + t) * 128 + j * 16;
            else { src = (const char*)hin16; sz = 0; }
            cpa16(sb + OFF_D0 + (uint32_t)g * STRIDE + j * 16, src, sz);
        }
    };
    auto stage_tapD = [&](int c, int buf) {
        #pragma unroll
        for (int it = 0; it < 4; ++it) {
            const int p = it * 256 + tid;
            const int row = p >> 3, j = p & 7;
            const char* src; int sz = 16;
            int tg = t0 + row + (c - 1) * dil;
            if (tg >= 0 && tg < TLEN)
                src = (const char*)hin16 + ((size_t)b * TLEN + tg) * 128 + j * 16;
            else { src = (const char*)hin16; sz = 0; }
            cpa16(sb + OFF_D0 + buf * RSZ + (uint32_t)row * STRIDE + j * 16, src, sz);
        }
    };
    auto stage_w2 = [&](int buf) {
        const char* wb = (const char*)(W216 + (size_t)l * 128 * 64);
        #pragma unroll
        for (int it = 0; it < 4; ++it) {
            const int p = it * 256 + tid;
            const int row = p >> 3, j = p & 7;
            cpa16(sb + OFF_W0 + buf * RSZ + (uint32_t)row * STRIDE + j * 16, wb + p * 16, 16);
        }
    };

    float acc[16][4];
    #pragma unroll
    for (int i = 0; i < 16; ++i)
        #pragma unroll
        for (int j2 = 0; j2 < 4; ++j2) acc[i][j2] = 0.f;

    auto do_mma = [&](uint32_t abase, uint32_t wbase, int nks) {
        for (int ks = 0; ks < nks; ++ks) {
            uint32_t a0f[4], a1f[4];
            ldm4(a0f, abase + ks * 32);
            ldm4(a1f, abase + 16 * STRIDE + ks * 32);
            uint32_t bf4[4][4];
            #pragma unroll
            for (int i = 0; i < 4; ++i)
                ldm4(bf4[i], wbase + (uint32_t)(nbase + i * 16 + lrow) * STRIDE + lkoff + ks * 32);
            #pragma unroll
            for (int i = 0; i < 4; ++i) {
                mma16816(acc[i * 2],         a0f, bf4[i][0], bf4[i][2]);
                mma16816(acc[i * 2 + 1],     a0f, bf4[i][1], bf4[i][3]);
            }
            #pragma unroll
            for (int i = 0; i < 4; ++i) {
                mma16816(acc[8 + i * 2],     a1f, bf4[i][0], bf4[i][2]);
                mma16816(acc[8 + i * 2 + 1], a1f, bf4[i][1], bf4[i][3]);
            }
        }
    };

    const uint32_t arow = (uint32_t)(mbase + lrow);
    uint32_t zoff;

    if (dil <= 64) {
        // ======== path A: cond first (pre-dependency), then union taps ========
        stage_W(3, 0); stage_condD(0, 0); CP_COMMIT();   // G1 (h-independent)
        stage_W(4, 1); stage_condD(1, 1); CP_COMMIT();   // G2 (h-independent)
        // p0: cond lo
        CP_WAIT1(); __syncthreads();
        do_mma(sb + OFF_D0 + arow * STRIDE + lkoff, sb + OFF_W0, 4);
        __syncthreads();
#if __CUDA_ARCH__ >= 900
        cudaGridDependencySynchronize();                 // wait for prev layer's h
#endif
        stage_W(0, 0); stage_DU(0, 128); CP_COMMIT();    // G3 (first h read)
        // p1: cond hi (16k)
        CP_WAIT1(); __syncthreads();
        do_mma(sb + OFF_D0 + RSZ + arow * STRIDE + lkoff, sb + OFF_W0 + RSZ, 1);
        __syncthreads();
        stage_W(1, 1); stage_DU(128, 2 * dil); CP_COMMIT(); // G4
        // p2: tap0
        CP_WAIT1(); __syncthreads();
        do_mma(sb + OFF_D0 + arow * STRIDE + lkoff, sb + OFF_W0, 4);
        __syncthreads();
        stage_W(2, 0); CP_COMMIT();                      // G5
        // p3: tap1
        CP_WAIT1(); __syncthreads();
        do_mma(sb + OFF_D0 + (arow + dil) * STRIDE + lkoff, sb + OFF_W0 + RSZ, 4);
        __syncthreads();
        stage_w2(1); CP_COMMIT();                        // G6
        // p4: tap2
        CP_WAIT1(); __syncthreads();
        do_mma(sb + OFF_D0 + (arow + 2 * dil) * STRIDE + lkoff, sb + OFF_W0, 4);
        __syncthreads();
        zoff = OFF_D0;
    } else {
        // ======== path B: per-tap pipeline ========
#if __CUDA_ARCH__ >= 900
        cudaGridDependencySynchronize();
#endif
        stage_W(0, 0); stage_tapD(0, 0); CP_COMMIT();
        stage_W(1, 1); stage_tapD(1, 1); CP_COMMIT();
        for (int c = 0; c < 5; ++c) {
            CP_WAIT1(); __syncthreads();
            const int buf = c & 1;
            do_mma(sb + OFF_D0 + buf * RSZ + arow * STRIDE + lkoff,
                   sb + OFF_W0 + buf * RSZ, (c == 4) ? 1 : 4);
            __syncthreads();
            if (c < 3) {
                const int nc = c + 2, nbuf = nc & 1;
                stage_W(nc, nbuf);
                if (nc < 3) stage_tapD(nc, nbuf);
                else        stage_condD(nc - 3, nbuf);
                CP_COMMIT();
            } else if (c == 3) { stage_w2(1); CP_COMMIT(); }
        }
        zoff = OFF_D0 + RSZ;
    }

    // ---------------- gate -> z (fp16), single-divide form --------------------
    #pragma unroll
    for (int mf = 0; mf < 2; ++mf) {
        const int tr0 = mbase + mf * 16 + r;
        #pragma unroll
        for (int i = 0; i < 4; ++i) {
            #pragma unroll
            for (int p = 0; p < 2; ++p) {
                const int j = (wn * 4 + i) * 8 + 2 * q + p;
                const float ba = sbd[j], bb = sbd[64 + j];
                const float* a = acc[(mf * 4 + i) * 2 + p];
                #pragma unroll
                for (int h = 0; h < 2; ++h) {
                    float xa = a[h * 2 + 0] + ba;
                    float xb = a[h * 2 + 1] + bb;
                    float e2a = __expf(-2.f * fabsf(xa));
                    float e2b = __expf(-xb);
                    float num = copysignf(1.f - e2a, xa);
                    float z   = __fdividef(num, (1.f + e2a) * (1.f + e2b));
                    const int tr = tr0 + h * 8;
                    *(__half*)(smem_c + zoff + (uint32_t)tr * STRIDE + j * 2) = __float2half(z);
                }
            }
        }
    }

    CP_WAIT0();
    __syncthreads();

    // ---------------- GEMM2: z * W2^T (W buf1) ----------------
    float acc2[16][4];
    #pragma unroll
    for (int i = 0; i < 16; ++i)
        #pragma unroll
        for (int j2 = 0; j2 < 4; ++j2) acc2[i][j2] = 0.f;

    #pragma unroll
    for (int ks = 0; ks < 4; ++ks) {
        uint32_t a0f[4], a1f[4];
        const uint32_t a0 = sb + zoff + arow * STRIDE + lkoff + ks * 32;
        ldm4(a0f, a0);
        ldm4(a1f, a0 + 16 * STRIDE);
        uint32_t wf4[4][4];
        #pragma unroll
        for (int i = 0; i < 4; ++i)
            ldm4(wf4[i], sb + OFF_W0 + RSZ + (uint32_t)(nbase + i * 16 + lrow) * STRIDE + lkoff + ks * 32);
        #pragma unroll
        for (int i = 0; i < 4; ++i) {
            mma16816(acc2[i * 2],         a0f, wf4[i][0], wf4[i][2]);
            mma16816(acc2[i * 2 + 1],     a0f, wf4[i][1], wf4[i][3]);
        }
        #pragma unroll
        for (int i = 0; i < 4; ++i) {
            mma16816(acc2[8 + i * 2],     a1f, wf4[i][0], wf4[i][2]);
            mma16816(acc2[8 + i * 2 + 1], a1f, wf4[i][1], wf4[i][3]);
        }
    }

    // ---------------- epilogue (warp-uniform, coalesced [t][ch]) -------------
    if (wn == 0) {                         // out-ch 0..63 -> skip
        #pragma unroll
        for (int mf = 0; mf < 2; ++mf) {
            const int trowA = t0 + mbase + mf * 16 + r;
            const int trowB = trowA + 8;
            #pragma unroll
            for (int i = 0; i < 4; ++i) {
                #pragma unroll
                for (int p = 0; p < 2; ++p) {
                    const int ch = i * 16 + p * 8 + 2 * q;
                    const float* d = acc2[(mf * 4 + i) * 2 + p];
                    float bs0 = sbd[128 + ch], bs1 = sbd[128 + ch + 1];
                    float2* p1 = (float2*)&skip[((size_t)b * TLEN + trowA) * 64 + ch];
                    float2* p2 = (float2*)&skip[((size_t)b * TLEN + trowB) * 64 + ch];
                    float2 v1 = *p1, v2 = *p2;
                    v1.x += d[0] + bs0; v1.y += d[1] + bs1;
                    v2.x += d[2] + bs0; v2.y += d[3] + bs1;
                    *p1 = v1; *p2 = v2;
                }
            }
        }
    } else {                               // out-ch 64..127 -> residual
        #pragma unroll
        for (int mf = 0; mf < 2; ++mf) {
            const int trowA = t0 + mbase + mf * 16 + r;
            const int trowB = trowA + 8;
            #pragma unroll
            for (int i = 0; i < 4; ++i) {
                #pragma unroll
                for (int p = 0; p < 2; ++p) {
                    const int ch = i * 16 + p * 8 + 2 * q;
                    const float* d = acc2[(mf * 4 + i) * 2 + p];
                    float br0 = sbd[192 + ch], br1 = sbd[192 + ch + 1];
                    size_t e1 = ((size_t)b * TLEN + trowA) * 64 + ch;
                    size_t e2 = ((size_t)b * TLEN + trowB) * 64 + ch;
                    float2 i1 = *(const float2*)&hin32[e1];
                    float2 i2 = *(const float2*)&hin32[e2];
                    float h10 = (d[0] + br0 + i1.x) * SQRT_HALF;
                    float h11 = (d[1] + br1 + i1.y) * SQRT_HALF;
                    float h20 = (d[2] + br0 + i2.x) * SQRT_HALF;
                    float h21 = (d[3] + br1 + i2.y) * SQRT_HALF;
                    *(float2*)&hout32[e1] = make_float2(h10, h11);
                    *(float2*)&hout32[e2] = make_float2(h20, h21);
                    *(uint32_t*)&hout16[e1] = packh2(h10, h11);
                    *(uint32_t*)&hout16[e2] = packh2(h20, h21);
                }
            }
        }
    }
}

// ======================= final head ==========================================
__global__ void final2(const float* __restrict__ skip,
                       const float* __restrict__ Wl1, const float* __restrict__ bl1,
                       const float* __restrict__ Wl2, const float* __restrict__ bl2,
                       float* __restrict__ out) {
    __shared__ float tile[128 * 65];
    __shared__ float b1s[64];
    __shared__ float W2s[64];
    int tid = threadIdx.x;   // 128
    if (tid < 64) { b1s[tid] = bl1[tid]; W2s[tid] = Wl2[tid]; }
    int t0 = (blockIdx.x & 255) * 128;
    int b  = blockIdx.x >> 8;
    for (int i = tid; i < 128 * 64; i += 128) {
        int rr = i >> 6, cc = i & 63;
        tile[rr * 65 + cc] = skip[((size_t)b * TLEN + t0) * 64 + i];
    }
    __syncthreads();
    float s1[64];
    #pragma unroll 8
    for (int j = 0; j < 64; ++j)
        s1[j] = fmaxf(tile[tid * 65 + j] * SQRT_INV_L, 0.f);
    float y2 = bl2[0];
    for (int o = 0; o < 64; ++o) {
        float a = b1s[o];
        #pragma unroll 8
        for (int j = 0; j < 64; ++j) a += Wl1[o * 64 + j] * s1[j];
        y2 += W2s[o] * fmaxf(a, 0.f);
    }
    out[(size_t)b * TLEN + t0 + tid] = y2;
}

// ======================= launch ==============================================
extern "C" void kernel_launch(void* const* d_in, const int* in_sizes, int n_in,
                              void* d_out, int out_size)
{
    const float* x       = (const float*)d_in[0];
    const float* c       = (const float*)d_in[1];
    const float* W_first = (const float*)d_in[2];
    const float* b_first = (const float*)d_in[3];
    const float* W_cin   = (const float*)d_in[4];
    const float* W_up    = (const float*)d_in[5];
    const float* Wd      = (const float*)d_in[6];
    const float* bd      = (const float*)d_in[7];
    const float* Wa      = (const float*)d_in[8];
    const float* Ws      = (const float*)d_in[9];
    const float* bs      = (const float*)d_in[10];
    const float* Wr      = (const float*)d_in[11];
    const float* br      = (const float*)d_in[12];
    const float* Wl1     = (const float*)d_in[13];
    const float* bl1     = (const float*)d_in[14];
    const float* Wl2     = (const float*)d_in[15];
    const float* bl2     = (const float*)d_in[16];
    float* out = (float*)d_out;

    float *skip, *h32a, *h32b;
    __half *h16a, *h16b, *c16, *Wg16, *W216;
    cudaGetSymbolAddress((void**)&skip, g_skip);
    cudaGetSymbolAddress((void**)&h32a, g_h32a);
    cudaGetSymbolAddress((void**)&h32b, g_h32b);
    cudaGetSymbolAddress((void**)&h16a, g_h16a);
    cudaGetSymbolAddress((void**)&h16b, g_h16b);
    cudaGetSymbolAddress((void**)&c16,  g_c16);
    cudaGetSymbolAddress((void**)&Wg16, g_Wg16);
    cudaGetSymbolAddress((void**)&W216, g_W216);

    const int COND_SMEM = (80 * 6 + 80 * 8 + 80 * 8 + 80 * 14 + 80 * 36 + 80 * 128) * 4;
    cudaFuncSetAttribute(cond_fused, cudaFuncAttributeMaxDynamicSharedMemorySize, COND_SMEM);
    cudaFuncSetAttribute(layer_mma, cudaFuncAttributeMaxDynamicSharedMemorySize, SMEM_NEED);

    {
        dim3 grid(TLEN / 128, NB);
        cond_fused<<<grid, 256, COND_SMEM>>>(c, W_cin, W_up, c16);
    }
    {
        int N = NLAYERS * 5 * 128 * 64 + NLAYERS * 128 * 64;
        prepack_w<<<(N + 255) / 256, 256>>>(Wd, Wa, Ws, Wr, Wg16, W216);
    }
    {
        int N = NB * TLEN * RC;
        first_pack<<<(N + 255) / 256, 256>>>(x, W_first, b_first, h32a, h16a, skip);
    }
    float *hi32 = h32a, *ho32 = h32b;
    __half *hi16 = h16a, *ho16 = h16b;
    for (int i = 0; i < NLAYERS; ++i) {
        int d = 1 << (i % 10);
        cudaLaunchConfig_t cfg = {};
        cfg.gridDim = dim3(TLEN / 128, NB);
        cfg.blockDim = dim3(256);
        cfg.dynamicSmemBytes = SMEM_NEED;
        cfg.stream = 0;
        cudaLaunchAttribute attrs[1];
        attrs[0].id = cudaLaunchAttributeProgrammaticStreamSerialization;
        attrs[0].val.programmaticStreamSerializationAllowed = 1;
        cfg.attrs = attrs;
        cfg.numAttrs = 1;
        cudaLaunchKernelEx(&cfg, layer_mma, i, d,
                           (const float*)hi32, ho32,
                           (const __half*)hi16, ho16,
                           (const __half*)c16, skip,
                           (const __half*)Wg16, (const __half*)W216,
                           bd, bs, br);
        { float* t = hi32; hi32 = ho32; ho32 = t; }
        { __half* t = hi16; hi16 = ho16; ho16 = t; }
    }
    final2<<<NB * (TLEN / 128), 128>>>(skip, Wl1, bl1, Wl2, bl2, out);
}